// round 8
// baseline (speedup 1.0000x reference)
#include <cuda_runtime.h>
#include <cuda_bf16.h>
#include <math.h>
#include <stdint.h>

#define BB 8
#define NN 100
#define DD 768
#define HH 768
#define TH 24
#define TT 577
#define IMGF 384.0f
#define M_ROWS 800
#define SPLIT 24
#define HSUB (HH / SPLIT)    // 32

// Scratch (device globals: allocation-free, graph-capture safe)
__device__ float g_rowsum[BB * TH * TH * DD];
__device__ __nv_bfloat16 g_pA[M_ROWS * DD];
__device__ __nv_bfloat16 g_pW[2 * DD * HH];
__device__ float g_ha[M_ROWS * HH];                 // pooled@W1[:D] + b1
__device__ float g_hb[M_ROWS * HH];                 // pooled@W1[D:]
__device__ float g_part[SPLIT * BB * NN * NN];      // pairwise partials, 7.7MB

// ---------------------------------------------------------------------------
// Kernel A (fused): blocks 0..191 row-prefix-sum the feature map;
// blocks 192..575 convert W1 fp32 -> bf16.
// ---------------------------------------------------------------------------
__global__ void prep_kernel(const float* __restrict__ tokens,
                            const float* __restrict__ W1) {
    if (blockIdx.x < BB * TH) {
        int by = blockIdx.x;
        int b = by / TH, y = by % TH;
        int t = threadIdx.x;
        const float* src = tokens + ((size_t)b * TT + 1 + y * TH) * DD + t;
        float* dst = g_rowsum + ((size_t)(b * TH + y) * TH) * DD + t;
        float run = 0.f;
        #pragma unroll
        for (int x = 0; x < TH; ++x) {
            run += src[(size_t)x * DD];
            dst[(size_t)x * DD] = run;
        }
    } else {
        int i = (blockIdx.x - BB * TH) * 768 + threadIdx.x;
        float4 v = ((const float4*)W1)[i];
        __nv_bfloat162* dst = (__nv_bfloat162*)(g_pW + (size_t)i * 4);
        dst[0] = __floats2bfloat162_rn(v.x, v.y);
        dst[1] = __floats2bfloat162_rn(v.z, v.w);
    }
}

// ---------------------------------------------------------------------------
// Kernel B: ROI pool from row-prefix sums -> pooled bf16.
// ---------------------------------------------------------------------------
__device__ __forceinline__ int to_patch(float v) {
    float pix = floorf(v * IMGF);
    return (int)floorf(pix / IMGF * (float)TH);
}

__global__ void pool_gather_kernel(const float* __restrict__ boxes) {
    int bn = blockIdx.x;
    int b = bn / NN;
    const float* box = boxes + (size_t)bn * 4;

    int px1 = min(max(to_patch(box[0]), 0), TH - 1);
    int py1 = min(max(to_patch(box[1]), 0), TH - 1);
    int px2 = min(max(to_patch(box[2]), 1), TH);
    int py2 = min(max(to_patch(box[3]), 1), TH);
    if (px2 <= px1) px2 = px1 + 1;
    if (py2 <= py1) py2 = py1 + 1;

    float inv = 1.0f / (float)((px2 - px1) * (py2 - py1));

    int t = threadIdx.x;
    const float* base = g_rowsum + (size_t)(b * TH * TH) * DD + t;
    float s = 0.f;
    for (int y = py1; y < py2; ++y) {
        const float* row = base + (size_t)(y * TH) * DD;
        float hi = row[(size_t)(px2 - 1) * DD];
        float lo = (px1 > 0) ? row[(size_t)(px1 - 1) * DD] : 0.f;
        s += hi - lo;
    }
    g_pA[(size_t)bn * DD + t] = __float2bfloat16_rn(s * inv);
}

// ---------------------------------------------------------------------------
// bf16 tensor-core GEMM: C[800,1536] = pooled[800,768] @ W[768,1536]
// cols 0-767 -> g_ha (+b1 fused), 768-1535 -> g_hb.
// ---------------------------------------------------------------------------
#define ASTR 40
#define BSTR 72

__global__ __launch_bounds__(256) void gemm_bf16_kernel(const float* __restrict__ b1) {
    __shared__ __nv_bfloat16 As[2][64 * ASTR];
    __shared__ __nv_bfloat16 Bs[2][32 * BSTR];

    int tid = threadIdx.x;
    int lane = tid & 31, wid = tid >> 5;
    int m0 = blockIdx.y * 64;
    int nblk = blockIdx.x;
    int half = (nblk >= 12);
    int n_in0 = nblk * 64 - half * 768;
    const __nv_bfloat16* Bg = g_pW + (size_t)half * DD * HH;

    int a_r = tid >> 2, a_c = (tid & 3) * 8;
    int b_r = tid >> 3, b_c = (tid & 7) * 8;
    int wm = (wid & 3) * 16, wn = (wid >> 2) * 32;

    float d[4][4];
    #pragma unroll
    for (int j = 0; j < 4; ++j)
        #pragma unroll
        for (int c = 0; c < 4; ++c) d[j][c] = 0.f;

    const uint4 z4 = make_uint4(0, 0, 0, 0);
    uint4 ra, rb;

    {
        int gr = m0 + a_r;
        ra = (gr < M_ROWS) ? *(const uint4*)(g_pA + (size_t)gr * DD + a_c) : z4;
        rb = *(const uint4*)(Bg + (size_t)b_r * HH + n_in0 + b_c);
        *(uint4*)(As[0] + a_r * ASTR + a_c) = ra;
        *(uint4*)(Bs[0] + b_r * BSTR + b_c) = rb;
    }
    __syncthreads();

    int lrow = (lane & 7) + ((lane >> 3) & 1) * 8;
    int lk8  = (lane >> 4) * 8;

    for (int it = 0; it < 24; ++it) {
        int buf = it & 1;
        if (it < 23) {
            int k0 = (it + 1) * 32;
            int gr = m0 + a_r;
            ra = (gr < M_ROWS) ? *(const uint4*)(g_pA + (size_t)gr * DD + k0 + a_c) : z4;
            rb = *(const uint4*)(Bg + (size_t)(k0 + b_r) * HH + n_in0 + b_c);
        }
        uint32_t abase = (uint32_t)__cvta_generic_to_shared(&As[buf][0]);
        uint32_t bbase = (uint32_t)__cvta_generic_to_shared(&Bs[buf][0]);

        #pragma unroll
        for (int kq = 0; kq < 32; kq += 16) {
            uint32_t a0, a1, a2, a3;
            uint32_t aaddr = abase + (uint32_t)(((wm + lrow) * ASTR + kq + lk8) * 2);
            asm volatile("ldmatrix.sync.aligned.m8n8.x4.shared.b16 {%0,%1,%2,%3}, [%4];"
                         : "=r"(a0), "=r"(a1), "=r"(a2), "=r"(a3) : "r"(aaddr));
            #pragma unroll
            for (int h = 0; h < 2; ++h) {
                uint32_t b0, b1r, b2, b3;
                uint32_t baddr = bbase + (uint32_t)(((kq + lrow) * BSTR + wn + h * 16 + lk8) * 2);
                asm volatile("ldmatrix.sync.aligned.m8n8.x4.trans.shared.b16 {%0,%1,%2,%3}, [%4];"
                             : "=r"(b0), "=r"(b1r), "=r"(b2), "=r"(b3) : "r"(baddr));
                asm volatile("mma.sync.aligned.m16n8k16.row.col.f32.bf16.bf16.f32 "
                             "{%0,%1,%2,%3}, {%4,%5,%6,%7}, {%8,%9}, {%0,%1,%2,%3};"
                             : "+f"(d[2*h][0]), "+f"(d[2*h][1]), "+f"(d[2*h][2]), "+f"(d[2*h][3])
                             : "r"(a0), "r"(a1), "r"(a2), "r"(a3), "r"(b0), "r"(b1r));
                asm volatile("mma.sync.aligned.m16n8k16.row.col.f32.bf16.bf16.f32 "
                             "{%0,%1,%2,%3}, {%4,%5,%6,%7}, {%8,%9}, {%0,%1,%2,%3};"
                             : "+f"(d[2*h+1][0]), "+f"(d[2*h+1][1]), "+f"(d[2*h+1][2]), "+f"(d[2*h+1][3])
                             : "r"(a0), "r"(a1), "r"(a2), "r"(a3), "r"(b2), "r"(b3));
            }
        }
        if (it < 23) {
            *(uint4*)(As[buf ^ 1] + a_r * ASTR + a_c) = ra;
            *(uint4*)(Bs[buf ^ 1] + b_r * BSTR + b_c) = rb;
            __syncthreads();
        }
    }

    float* dst = half ? g_hb : g_ha;
    int row0 = m0 + wm + (lane >> 2);
    #pragma unroll
    for (int j = 0; j < 4; ++j) {
        int col = n_in0 + wn + j * 8 + (lane & 3) * 2;
        float bx = 0.f, by = 0.f;
        if (!half) { bx = b1[col]; by = b1[col + 1]; }
        if (row0 < M_ROWS) {
            float2 v = make_float2(d[j][0] + bx, d[j][1] + by);
            *(float2*)(dst + (size_t)row0 * HH + col) = v;
        }
        if (row0 + 8 < M_ROWS) {
            float2 v = make_float2(d[j][2] + bx, d[j][3] + by);
            *(float2*)(dst + (size_t)(row0 + 8) * HH + col) = v;
        }
    }
}

// ---------------------------------------------------------------------------
// Pairwise v6: fine-grained blocks for wave balance. One block = 50x100
// outputs for one (h-split, i-half, batch): grid (24, 2, 8) = 384 blocks,
// 250 threads (ty 0..9 x tx 0..24), each owns 5x4 outputs (20 ILP chains).
// HSUB=32 h per block, single smem fill + one sync.
// ---------------------------------------------------------------------------
__global__ __launch_bounds__(256) void pairwise_kernel(const float* __restrict__ W2) {
    __shared__ float sA[HSUB][NN / 2];
    __shared__ float sB[HSUB][NN];
    __shared__ float sW[HSUB];

    int s = blockIdx.x;                  // 0..23 (h split)
    int ihalf = blockIdx.y;              // 0..1
    int b = blockIdx.z;
    int hbase = s * HSUB;
    int i0 = ihalf * (NN / 2);

    int tid = threadIdx.x;               // 0..249
    int ty = tid / 25;                   // 0..9   (i: rows 5*ty..5*ty+4 within half)
    int tx = tid % 25;                   // 0..24  (j: cols 4*tx..4*tx+3)

    const float* haB = g_ha + ((size_t)b * NN + i0) * HH + hbase;
    const float* hbB = g_hb + ((size_t)b * NN) * HH + hbase;

    // fill: sA 50x32, sB 100x32 (transposed: consecutive tid -> consecutive h)
    for (int idx = tid; idx < (NN / 2) * HSUB; idx += 250) {
        int row = idx / HSUB, hl = idx % HSUB;
        sA[hl][row] = haB[(size_t)row * HH + hl];
    }
    for (int idx = tid; idx < NN * HSUB; idx += 250) {
        int row = idx / HSUB, hl = idx % HSUB;
        sB[hl][row] = hbB[(size_t)row * HH + hl];
    }
    if (tid < HSUB) sW[tid] = W2[hbase + tid];
    __syncthreads();

    float acc[5][4];
    #pragma unroll
    for (int r = 0; r < 5; ++r)
        #pragma unroll
        for (int c = 0; c < 4; ++c) acc[r][c] = 0.f;

    #pragma unroll 4
    for (int h = 0; h < HSUB; ++h) {
        float w = sW[h];
        float ar[5];
        #pragma unroll
        for (int r = 0; r < 5; ++r) ar[r] = sA[h][5 * ty + r];
        float4 bv = *(const float4*)&sB[h][4 * tx];
        float br[4] = {bv.x, bv.y, bv.z, bv.w};
        #pragma unroll
        for (int r = 0; r < 5; ++r)
            #pragma unroll
            for (int c = 0; c < 4; ++c)
                acc[r][c] += fmaxf(ar[r] + br[c], 0.f) * w;
    }

    float* dst = g_part + ((size_t)(s * BB + b) * NN + i0) * NN;
    #pragma unroll
    for (int r = 0; r < 5; ++r) {
        float4 v = make_float4(acc[r][0], acc[r][1], acc[r][2], acc[r][3]);
        *(float4*)(dst + (size_t)(5 * ty + r) * NN + 4 * tx) = v;
    }
}

// ---------------------------------------------------------------------------
// Combine: sum 24 partials + b2, sigmoid, write out[b,i,j].
// ---------------------------------------------------------------------------
__global__ void combine_kernel(const float* __restrict__ b2,
                               float* __restrict__ out) {
    int b = blockIdx.y;
    int idx = blockIdx.x * 256 + threadIdx.x;
    if (idx >= NN * NN) return;

    float x = b2[0];
    #pragma unroll
    for (int s = 0; s < SPLIT; ++s)
        x += g_part[((size_t)(s * BB + b) * NN * NN) + idx];
    out[(size_t)b * NN * NN + idx] = 1.f / (1.f + expf(-x));
}

// ---------------------------------------------------------------------------
// Launch
// ---------------------------------------------------------------------------
extern "C" void kernel_launch(void* const* d_in, const int* in_sizes, int n_in,
                              void* d_out, int out_size) {
    const float* patch_tokens = (const float*)d_in[0];
    const float* boxes        = (const float*)d_in[1];
    const float* W1           = (const float*)d_in[2];
    const float* b1           = (const float*)d_in[3];
    const float* W2           = (const float*)d_in[4];
    const float* b2           = (const float*)d_in[5];
    float* out = (float*)d_out;

    prep_kernel<<<BB * TH + 384, DD>>>(patch_tokens, W1);
    pool_gather_kernel<<<M_ROWS, DD>>>(boxes);

    dim3 ggrid(24, 13);
    gemm_bf16_kernel<<<ggrid, 256>>>(b1);

    dim3 pgrid(SPLIT, 2, BB);                    // 384 blocks, 250 thr
    pairwise_kernel<<<pgrid, 250>>>(W2);

    dim3 cgrid((NN * NN + 255) / 256, BB);       // (40, 8)
    combine_kernel<<<cgrid, 256>>>(b2, out);
}

// round 9
// speedup vs baseline: 1.1278x; 1.1278x over previous
#include <cuda_runtime.h>
#include <cuda_bf16.h>
#include <math.h>
#include <stdint.h>

#define BB 8
#define NN 100
#define DD 768
#define HH 768
#define TH 24
#define TT 577
#define IMGF 384.0f
#define M_ROWS 800
#define SPLIT 24
#define HSUB (HH / SPLIT)    // 32

// Scratch (device globals: allocation-free, graph-capture safe)
__device__ float g_rowsum[BB * TH * TH * DD];
__device__ __nv_bfloat16 g_pA[M_ROWS * DD];
__device__ __nv_bfloat16 g_pW[2 * DD * HH];
__device__ float g_ha[M_ROWS * HH];                 // pooled@W1[:D] + b1
__device__ float g_hb[M_ROWS * HH];                 // pooled@W1[D:]
__device__ float g_part[SPLIT * BB * NN * NN];      // pairwise partials, 7.7MB

// Packed fp32x2 helpers (sm_100+; identical rn rounding to scalar)
union F2U { unsigned long long u; float2 f; };
#define ADD2(o, a, b) asm("add.rn.f32x2 %0, %1, %2;" : "=l"(o) : "l"(a), "l"(b))
#define FMA2(o, a, b, c) asm("fma.rn.f32x2 %0, %1, %2, %3;" : "=l"(o) : "l"(a), "l"(b), "l"(c))
__device__ __forceinline__ unsigned long long pack2(float lo, float hi) {
    unsigned long long r;
    asm("mov.b64 %0, {%1, %2};" : "=l"(r) : "f"(lo), "f"(hi));
    return r;
}

// ---------------------------------------------------------------------------
// Kernel A (fused): blocks 0..191 row-prefix-sum the feature map;
// blocks 192..575 convert W1 fp32 -> bf16.
// ---------------------------------------------------------------------------
__global__ void prep_kernel(const float* __restrict__ tokens,
                            const float* __restrict__ W1) {
    if (blockIdx.x < BB * TH) {
        int by = blockIdx.x;
        int b = by / TH, y = by % TH;
        int t = threadIdx.x;
        const float* src = tokens + ((size_t)b * TT + 1 + y * TH) * DD + t;
        float* dst = g_rowsum + ((size_t)(b * TH + y) * TH) * DD + t;
        float run = 0.f;
        #pragma unroll
        for (int x = 0; x < TH; ++x) {
            run += src[(size_t)x * DD];
            dst[(size_t)x * DD] = run;
        }
    } else {
        int i = (blockIdx.x - BB * TH) * 768 + threadIdx.x;
        float4 v = ((const float4*)W1)[i];
        __nv_bfloat162* dst = (__nv_bfloat162*)(g_pW + (size_t)i * 4);
        dst[0] = __floats2bfloat162_rn(v.x, v.y);
        dst[1] = __floats2bfloat162_rn(v.z, v.w);
    }
}

// ---------------------------------------------------------------------------
// Kernel B: ROI pool from row-prefix sums -> pooled bf16.
// 256 threads, 3 channels per thread (6 independent loads in flight per y).
// ---------------------------------------------------------------------------
__device__ __forceinline__ int to_patch(float v) {
    float pix = floorf(v * IMGF);
    return (int)floorf(pix / IMGF * (float)TH);
}

__global__ void pool_gather_kernel(const float* __restrict__ boxes) {
    int bn = blockIdx.x;
    int b = bn / NN;
    const float* box = boxes + (size_t)bn * 4;

    int px1 = min(max(to_patch(box[0]), 0), TH - 1);
    int py1 = min(max(to_patch(box[1]), 0), TH - 1);
    int px2 = min(max(to_patch(box[2]), 1), TH);
    int py2 = min(max(to_patch(box[3]), 1), TH);
    if (px2 <= px1) px2 = px1 + 1;
    if (py2 <= py1) py2 = py1 + 1;

    float inv = 1.0f / (float)((px2 - px1) * (py2 - py1));

    int t = threadIdx.x;                 // 0..255
    const float* base = g_rowsum + (size_t)(b * TH * TH) * DD;
    float s0 = 0.f, s1 = 0.f, s2 = 0.f;
    for (int y = py1; y < py2; ++y) {
        const float* rhi = base + ((size_t)(y * TH) + (px2 - 1)) * DD;
        float h0 = rhi[t], h1 = rhi[t + 256], h2 = rhi[t + 512];
        float l0 = 0.f, l1 = 0.f, l2 = 0.f;
        if (px1 > 0) {
            const float* rlo = base + ((size_t)(y * TH) + (px1 - 1)) * DD;
            l0 = rlo[t]; l1 = rlo[t + 256]; l2 = rlo[t + 512];
        }
        s0 += h0 - l0; s1 += h1 - l1; s2 += h2 - l2;
    }
    __nv_bfloat16* dst = g_pA + (size_t)bn * DD;
    dst[t]       = __float2bfloat16_rn(s0 * inv);
    dst[t + 256] = __float2bfloat16_rn(s1 * inv);
    dst[t + 512] = __float2bfloat16_rn(s2 * inv);
}

// ---------------------------------------------------------------------------
// bf16 tensor-core GEMM: C[800,1536] = pooled[800,768] @ W[768,1536]
// cols 0-767 -> g_ha (+b1 fused), 768-1535 -> g_hb.
// ---------------------------------------------------------------------------
#define ASTR 40
#define BSTR 72

__global__ __launch_bounds__(256) void gemm_bf16_kernel(const float* __restrict__ b1) {
    __shared__ __nv_bfloat16 As[2][64 * ASTR];
    __shared__ __nv_bfloat16 Bs[2][32 * BSTR];

    int tid = threadIdx.x;
    int lane = tid & 31, wid = tid >> 5;
    int m0 = blockIdx.y * 64;
    int nblk = blockIdx.x;
    int half = (nblk >= 12);
    int n_in0 = nblk * 64 - half * 768;
    const __nv_bfloat16* Bg = g_pW + (size_t)half * DD * HH;

    int a_r = tid >> 2, a_c = (tid & 3) * 8;
    int b_r = tid >> 3, b_c = (tid & 7) * 8;
    int wm = (wid & 3) * 16, wn = (wid >> 2) * 32;

    float d[4][4];
    #pragma unroll
    for (int j = 0; j < 4; ++j)
        #pragma unroll
        for (int c = 0; c < 4; ++c) d[j][c] = 0.f;

    const uint4 z4 = make_uint4(0, 0, 0, 0);
    uint4 ra, rb;

    {
        int gr = m0 + a_r;
        ra = (gr < M_ROWS) ? *(const uint4*)(g_pA + (size_t)gr * DD + a_c) : z4;
        rb = *(const uint4*)(Bg + (size_t)b_r * HH + n_in0 + b_c);
        *(uint4*)(As[0] + a_r * ASTR + a_c) = ra;
        *(uint4*)(Bs[0] + b_r * BSTR + b_c) = rb;
    }
    __syncthreads();

    int lrow = (lane & 7) + ((lane >> 3) & 1) * 8;
    int lk8  = (lane >> 4) * 8;

    for (int it = 0; it < 24; ++it) {
        int buf = it & 1;
        if (it < 23) {
            int k0 = (it + 1) * 32;
            int gr = m0 + a_r;
            ra = (gr < M_ROWS) ? *(const uint4*)(g_pA + (size_t)gr * DD + k0 + a_c) : z4;
            rb = *(const uint4*)(Bg + (size_t)(k0 + b_r) * HH + n_in0 + b_c);
        }
        uint32_t abase = (uint32_t)__cvta_generic_to_shared(&As[buf][0]);
        uint32_t bbase = (uint32_t)__cvta_generic_to_shared(&Bs[buf][0]);

        #pragma unroll
        for (int kq = 0; kq < 32; kq += 16) {
            uint32_t a0, a1, a2, a3;
            uint32_t aaddr = abase + (uint32_t)(((wm + lrow) * ASTR + kq + lk8) * 2);
            asm volatile("ldmatrix.sync.aligned.m8n8.x4.shared.b16 {%0,%1,%2,%3}, [%4];"
                         : "=r"(a0), "=r"(a1), "=r"(a2), "=r"(a3) : "r"(aaddr));
            #pragma unroll
            for (int h = 0; h < 2; ++h) {
                uint32_t b0, b1r, b2, b3;
                uint32_t baddr = bbase + (uint32_t)(((kq + lrow) * BSTR + wn + h * 16 + lk8) * 2);
                asm volatile("ldmatrix.sync.aligned.m8n8.x4.trans.shared.b16 {%0,%1,%2,%3}, [%4];"
                             : "=r"(b0), "=r"(b1r), "=r"(b2), "=r"(b3) : "r"(baddr));
                asm volatile("mma.sync.aligned.m16n8k16.row.col.f32.bf16.bf16.f32 "
                             "{%0,%1,%2,%3}, {%4,%5,%6,%7}, {%8,%9}, {%0,%1,%2,%3};"
                             : "+f"(d[2*h][0]), "+f"(d[2*h][1]), "+f"(d[2*h][2]), "+f"(d[2*h][3])
                             : "r"(a0), "r"(a1), "r"(a2), "r"(a3), "r"(b0), "r"(b1r));
                asm volatile("mma.sync.aligned.m16n8k16.row.col.f32.bf16.bf16.f32 "
                             "{%0,%1,%2,%3}, {%4,%5,%6,%7}, {%8,%9}, {%0,%1,%2,%3};"
                             : "+f"(d[2*h+1][0]), "+f"(d[2*h+1][1]), "+f"(d[2*h+1][2]), "+f"(d[2*h+1][3])
                             : "r"(a0), "r"(a1), "r"(a2), "r"(a3), "r"(b2), "r"(b3));
            }
        }
        if (it < 23) {
            *(uint4*)(As[buf ^ 1] + a_r * ASTR + a_c) = ra;
            *(uint4*)(Bs[buf ^ 1] + b_r * BSTR + b_c) = rb;
            __syncthreads();
        }
    }

    float* dst = half ? g_hb : g_ha;
    int row0 = m0 + wm + (lane >> 2);
    #pragma unroll
    for (int j = 0; j < 4; ++j) {
        int col = n_in0 + wn + j * 8 + (lane & 3) * 2;
        float bx = 0.f, by = 0.f;
        if (!half) { bx = b1[col]; by = b1[col + 1]; }
        if (row0 < M_ROWS) {
            float2 v = make_float2(d[j][0] + bx, d[j][1] + by);
            *(float2*)(dst + (size_t)row0 * HH + col) = v;
        }
        if (row0 + 8 < M_ROWS) {
            float2 v = make_float2(d[j][2] + bx, d[j][3] + by);
            *(float2*)(dst + (size_t)(row0 + 8) * HH + col) = v;
        }
    }
}

// ---------------------------------------------------------------------------
// Pairwise v7 = v5 geometry + packed f32x2 math.  One block = full 100x100
// output for one (h-split, batch); 500 threads (20x25), 5x4 outputs each.
// j-columns packed in pairs: ADD2 / 2x FMNMX / FMA2 per pair.
// ---------------------------------------------------------------------------
__global__ __launch_bounds__(512, 2) void pairwise_kernel(const float* __restrict__ W2) {
    __shared__ float sA[HSUB][NN];
    __shared__ float sB[HSUB][NN];
    __shared__ float sW[HSUB];

    int s = blockIdx.x;                  // 0..23 (h split)
    int b = blockIdx.y;
    int hbase = s * HSUB;

    int tid = threadIdx.x;               // 0..499
    int ty = tid / 25;                   // 0..19
    int tx = tid % 25;                   // 0..24

    const float* haB = g_ha + ((size_t)b * NN) * HH + hbase;
    const float* hbB = g_hb + ((size_t)b * NN) * HH + hbase;

    for (int idx = tid; idx < NN * HSUB; idx += 500) {
        int row = idx / HSUB, hl = idx % HSUB;
        sA[hl][row] = haB[(size_t)row * HH + hl];
        sB[hl][row] = hbB[(size_t)row * HH + hl];
    }
    if (tid < HSUB) sW[tid] = W2[hbase + tid];
    __syncthreads();

    F2U acc[5][2];
    #pragma unroll
    for (int r = 0; r < 5; ++r) {
        acc[r][0].f = make_float2(0.f, 0.f);
        acc[r][1].f = make_float2(0.f, 0.f);
    }

    #pragma unroll 4
    for (int h = 0; h < HSUB; ++h) {
        float w = sW[h];
        unsigned long long w2 = pack2(w, w);
        float4 bv = *(const float4*)&sB[h][4 * tx];
        unsigned long long bp0 = pack2(bv.x, bv.y);
        unsigned long long bp1 = pack2(bv.z, bv.w);
        #pragma unroll
        for (int r = 0; r < 5; ++r) {
            float a = sA[h][5 * ty + r];
            unsigned long long a2 = pack2(a, a);
            F2U v0, v1;
            ADD2(v0.u, a2, bp0);
            ADD2(v1.u, a2, bp1);
            v0.f.x = fmaxf(v0.f.x, 0.f); v0.f.y = fmaxf(v0.f.y, 0.f);
            v1.f.x = fmaxf(v1.f.x, 0.f); v1.f.y = fmaxf(v1.f.y, 0.f);
            FMA2(acc[r][0].u, v0.u, w2, acc[r][0].u);
            FMA2(acc[r][1].u, v1.u, w2, acc[r][1].u);
        }
    }

    float* dst = g_part + ((size_t)(s * BB + b) * NN) * NN;
    #pragma unroll
    for (int r = 0; r < 5; ++r) {
        float4 v = make_float4(acc[r][0].f.x, acc[r][0].f.y,
                               acc[r][1].f.x, acc[r][1].f.y);
        *(float4*)(dst + (size_t)(5 * ty + r) * NN + 4 * tx) = v;
    }
}

// ---------------------------------------------------------------------------
// Combine: sum 24 partials + b2, sigmoid, write out[b,i,j].
// ---------------------------------------------------------------------------
__global__ void combine_kernel(const float* __restrict__ b2,
                               float* __restrict__ out) {
    int b = blockIdx.y;
    int idx = blockIdx.x * 256 + threadIdx.x;
    if (idx >= NN * NN) return;

    float x = b2[0];
    #pragma unroll
    for (int s = 0; s < SPLIT; ++s)
        x += g_part[((size_t)(s * BB + b) * NN * NN) + idx];
    out[(size_t)b * NN * NN + idx] = 1.f / (1.f + expf(-x));
}

// ---------------------------------------------------------------------------
// Launch
// ---------------------------------------------------------------------------
extern "C" void kernel_launch(void* const* d_in, const int* in_sizes, int n_in,
                              void* d_out, int out_size) {
    const float* patch_tokens = (const float*)d_in[0];
    const float* boxes        = (const float*)d_in[1];
    const float* W1           = (const float*)d_in[2];
    const float* b1           = (const float*)d_in[3];
    const float* W2           = (const float*)d_in[4];
    const float* b2           = (const float*)d_in[5];
    float* out = (float*)d_out;

    prep_kernel<<<BB * TH + 384, DD>>>(patch_tokens, W1);
    pool_gather_kernel<<<M_ROWS, 256>>>(boxes);

    dim3 ggrid(24, 13);
    gemm_bf16_kernel<<<ggrid, 256>>>(b1);

    dim3 pgrid(SPLIT, BB);                       // 192 blocks, 500 thr
    pairwise_kernel<<<pgrid, 500>>>(W2);

    dim3 cgrid((NN * NN + 255) / 256, BB);       // (40, 8)
    combine_kernel<<<cgrid, 256>>>(b2, out);
}

// round 10
// speedup vs baseline: 1.1354x; 1.0067x over previous
#include <cuda_runtime.h>
#include <cuda_bf16.h>
#include <math.h>
#include <stdint.h>

#define BB 8
#define NN 100
#define DD 768
#define HH 768
#define TH 24
#define TT 577
#define IMGF 384.0f
#define M_ROWS 800
#define SPLIT 16
#define HSUB (HH / SPLIT)    // 48

// Scratch (device globals: allocation-free, graph-capture safe)
__device__ float g_rowsum[BB * TH * TH * DD];
__device__ __nv_bfloat16 g_pA[M_ROWS * DD];
__device__ __nv_bfloat16 g_pW[2 * DD * HH];
__device__ float g_ha[M_ROWS * HH];                 // pooled@W1[:D] + b1
__device__ float g_hb[M_ROWS * HH];                 // pooled@W1[D:]
__device__ float g_part[SPLIT * BB * NN * NN];      // pairwise partials

// Packed fp32x2 helpers (sm_100+; identical rn rounding to scalar)
union F2U { unsigned long long u; float2 f; };
#define ADD2(o, a, b) asm("add.rn.f32x2 %0, %1, %2;" : "=l"(o) : "l"(a), "l"(b))
#define FMA2(o, a, b, c) asm("fma.rn.f32x2 %0, %1, %2, %3;" : "=l"(o) : "l"(a), "l"(b), "l"(c))
__device__ __forceinline__ unsigned long long pack2(float lo, float hi) {
    unsigned long long r;
    asm("mov.b64 %0, {%1, %2};" : "=l"(r) : "f"(lo), "f"(hi));
    return r;
}

// ---------------------------------------------------------------------------
// Kernel A (fused): blocks 0..191 row-prefix-sum the feature map;
// blocks 192..575 convert W1 fp32 -> bf16.
// ---------------------------------------------------------------------------
__global__ void prep_kernel(const float* __restrict__ tokens,
                            const float* __restrict__ W1) {
    if (blockIdx.x < BB * TH) {
        int by = blockIdx.x;
        int b = by / TH, y = by % TH;
        int t = threadIdx.x;
        const float* src = tokens + ((size_t)b * TT + 1 + y * TH) * DD + t;
        float* dst = g_rowsum + ((size_t)(b * TH + y) * TH) * DD + t;
        float run = 0.f;
        #pragma unroll
        for (int x = 0; x < TH; ++x) {
            run += src[(size_t)x * DD];
            dst[(size_t)x * DD] = run;
        }
    } else {
        int i = (blockIdx.x - BB * TH) * 768 + threadIdx.x;
        float4 v = ((const float4*)W1)[i];
        __nv_bfloat162* dst = (__nv_bfloat162*)(g_pW + (size_t)i * 4);
        dst[0] = __floats2bfloat162_rn(v.x, v.y);
        dst[1] = __floats2bfloat162_rn(v.z, v.w);
    }
}

// ---------------------------------------------------------------------------
// Kernel B: ROI pool from row-prefix sums -> pooled bf16.
// 256 threads, 3 channels per thread (6 independent loads in flight per y).
// ---------------------------------------------------------------------------
__device__ __forceinline__ int to_patch(float v) {
    float pix = floorf(v * IMGF);
    return (int)floorf(pix / IMGF * (float)TH);
}

__global__ void pool_gather_kernel(const float* __restrict__ boxes) {
    int bn = blockIdx.x;
    int b = bn / NN;
    const float* box = boxes + (size_t)bn * 4;

    int px1 = min(max(to_patch(box[0]), 0), TH - 1);
    int py1 = min(max(to_patch(box[1]), 0), TH - 1);
    int px2 = min(max(to_patch(box[2]), 1), TH);
    int py2 = min(max(to_patch(box[3]), 1), TH);
    if (px2 <= px1) px2 = px1 + 1;
    if (py2 <= py1) py2 = py1 + 1;

    float inv = 1.0f / (float)((px2 - px1) * (py2 - py1));

    int t = threadIdx.x;                 // 0..255
    const float* base = g_rowsum + (size_t)(b * TH * TH) * DD;
    float s0 = 0.f, s1 = 0.f, s2 = 0.f;
    for (int y = py1; y < py2; ++y) {
        const float* rhi = base + ((size_t)(y * TH) + (px2 - 1)) * DD;
        float h0 = rhi[t], h1 = rhi[t + 256], h2 = rhi[t + 512];
        float l0 = 0.f, l1 = 0.f, l2 = 0.f;
        if (px1 > 0) {
            const float* rlo = base + ((size_t)(y * TH) + (px1 - 1)) * DD;
            l0 = rlo[t]; l1 = rlo[t + 256]; l2 = rlo[t + 512];
        }
        s0 += h0 - l0; s1 += h1 - l1; s2 += h2 - l2;
    }
    __nv_bfloat16* dst = g_pA + (size_t)bn * DD;
    dst[t]       = __float2bfloat16_rn(s0 * inv);
    dst[t + 256] = __float2bfloat16_rn(s1 * inv);
    dst[t + 512] = __float2bfloat16_rn(s2 * inv);
}

// ---------------------------------------------------------------------------
// bf16 tensor-core GEMM: C[800,1536] = pooled[800,768] @ W[768,1536]
// cols 0-767 -> g_ha (+b1 fused), 768-1535 -> g_hb.
// ---------------------------------------------------------------------------
#define ASTR 40
#define BSTR 72

__global__ __launch_bounds__(256) void gemm_bf16_kernel(const float* __restrict__ b1) {
    __shared__ __nv_bfloat16 As[2][64 * ASTR];
    __shared__ __nv_bfloat16 Bs[2][32 * BSTR];

    int tid = threadIdx.x;
    int lane = tid & 31, wid = tid >> 5;
    int m0 = blockIdx.y * 64;
    int nblk = blockIdx.x;
    int half = (nblk >= 12);
    int n_in0 = nblk * 64 - half * 768;
    const __nv_bfloat16* Bg = g_pW + (size_t)half * DD * HH;

    int a_r = tid >> 2, a_c = (tid & 3) * 8;
    int b_r = tid >> 3, b_c = (tid & 7) * 8;
    int wm = (wid & 3) * 16, wn = (wid >> 2) * 32;

    float d[4][4];
    #pragma unroll
    for (int j = 0; j < 4; ++j)
        #pragma unroll
        for (int c = 0; c < 4; ++c) d[j][c] = 0.f;

    const uint4 z4 = make_uint4(0, 0, 0, 0);
    uint4 ra, rb;

    {
        int gr = m0 + a_r;
        ra = (gr < M_ROWS) ? *(const uint4*)(g_pA + (size_t)gr * DD + a_c) : z4;
        rb = *(const uint4*)(Bg + (size_t)b_r * HH + n_in0 + b_c);
        *(uint4*)(As[0] + a_r * ASTR + a_c) = ra;
        *(uint4*)(Bs[0] + b_r * BSTR + b_c) = rb;
    }
    __syncthreads();

    int lrow = (lane & 7) + ((lane >> 3) & 1) * 8;
    int lk8  = (lane >> 4) * 8;

    for (int it = 0; it < 24; ++it) {
        int buf = it & 1;
        if (it < 23) {
            int k0 = (it + 1) * 32;
            int gr = m0 + a_r;
            ra = (gr < M_ROWS) ? *(const uint4*)(g_pA + (size_t)gr * DD + k0 + a_c) : z4;
            rb = *(const uint4*)(Bg + (size_t)(k0 + b_r) * HH + n_in0 + b_c);
        }
        uint32_t abase = (uint32_t)__cvta_generic_to_shared(&As[buf][0]);
        uint32_t bbase = (uint32_t)__cvta_generic_to_shared(&Bs[buf][0]);

        #pragma unroll
        for (int kq = 0; kq < 32; kq += 16) {
            uint32_t a0, a1, a2, a3;
            uint32_t aaddr = abase + (uint32_t)(((wm + lrow) * ASTR + kq + lk8) * 2);
            asm volatile("ldmatrix.sync.aligned.m8n8.x4.shared.b16 {%0,%1,%2,%3}, [%4];"
                         : "=r"(a0), "=r"(a1), "=r"(a2), "=r"(a3) : "r"(aaddr));
            #pragma unroll
            for (int h = 0; h < 2; ++h) {
                uint32_t b0, b1r, b2, b3;
                uint32_t baddr = bbase + (uint32_t)(((kq + lrow) * BSTR + wn + h * 16 + lk8) * 2);
                asm volatile("ldmatrix.sync.aligned.m8n8.x4.trans.shared.b16 {%0,%1,%2,%3}, [%4];"
                             : "=r"(b0), "=r"(b1r), "=r"(b2), "=r"(b3) : "r"(baddr));
                asm volatile("mma.sync.aligned.m16n8k16.row.col.f32.bf16.bf16.f32 "
                             "{%0,%1,%2,%3}, {%4,%5,%6,%7}, {%8,%9}, {%0,%1,%2,%3};"
                             : "+f"(d[2*h][0]), "+f"(d[2*h][1]), "+f"(d[2*h][2]), "+f"(d[2*h][3])
                             : "r"(a0), "r"(a1), "r"(a2), "r"(a3), "r"(b0), "r"(b1r));
                asm volatile("mma.sync.aligned.m16n8k16.row.col.f32.bf16.bf16.f32 "
                             "{%0,%1,%2,%3}, {%4,%5,%6,%7}, {%8,%9}, {%0,%1,%2,%3};"
                             : "+f"(d[2*h+1][0]), "+f"(d[2*h+1][1]), "+f"(d[2*h+1][2]), "+f"(d[2*h+1][3])
                             : "r"(a0), "r"(a1), "r"(a2), "r"(a3), "r"(b2), "r"(b3));
            }
        }
        if (it < 23) {
            *(uint4*)(As[buf ^ 1] + a_r * ASTR + a_c) = ra;
            *(uint4*)(Bs[buf ^ 1] + b_r * BSTR + b_c) = rb;
            __syncthreads();
        }
    }

    float* dst = half ? g_hb : g_ha;
    int row0 = m0 + wm + (lane >> 2);
    #pragma unroll
    for (int j = 0; j < 4; ++j) {
        int col = n_in0 + wn + j * 8 + (lane & 3) * 2;
        float bx = 0.f, by = 0.f;
        if (!half) { bx = b1[col]; by = b1[col + 1]; }
        if (row0 < M_ROWS) {
            float2 v = make_float2(d[j][0] + bx, d[j][1] + by);
            *(float2*)(dst + (size_t)row0 * HH + col) = v;
        }
        if (row0 + 8 < M_ROWS) {
            float2 v = make_float2(d[j][2] + bx, d[j][3] + by);
            *(float2*)(dst + (size_t)(row0 + 8) * HH + col) = v;
        }
    }
}

// ---------------------------------------------------------------------------
// Pairwise v8 = v7 math, SPLIT=16 -> 128 blocks = one wave (no quantization).
// One block = full 100x100 output for one (h-split, batch); 500 threads
// (20x25), 5x4 outputs each, HSUB=48 h per block.
// ---------------------------------------------------------------------------
__global__ __launch_bounds__(512, 1) void pairwise_kernel(const float* __restrict__ W2) {
    __shared__ float sA[HSUB][NN];
    __shared__ float sB[HSUB][NN];
    __shared__ float sW[HSUB];

    int s = blockIdx.x;                  // 0..15 (h split)
    int b = blockIdx.y;
    int hbase = s * HSUB;

    int tid = threadIdx.x;               // 0..499
    int ty = tid / 25;                   // 0..19
    int tx = tid % 25;                   // 0..24

    const float* haB = g_ha + ((size_t)b * NN) * HH + hbase;
    const float* hbB = g_hb + ((size_t)b * NN) * HH + hbase;

    for (int idx = tid; idx < NN * HSUB; idx += 500) {
        int row = idx / HSUB, hl = idx % HSUB;
        sA[hl][row] = haB[(size_t)row * HH + hl];
        sB[hl][row] = hbB[(size_t)row * HH + hl];
    }
    if (tid < HSUB) sW[tid] = W2[hbase + tid];
    __syncthreads();

    F2U acc[5][2];
    #pragma unroll
    for (int r = 0; r < 5; ++r) {
        acc[r][0].f = make_float2(0.f, 0.f);
        acc[r][1].f = make_float2(0.f, 0.f);
    }

    #pragma unroll 4
    for (int h = 0; h < HSUB; ++h) {
        float w = sW[h];
        unsigned long long w2 = pack2(w, w);
        float4 bv = *(const float4*)&sB[h][4 * tx];
        unsigned long long bp0 = pack2(bv.x, bv.y);
        unsigned long long bp1 = pack2(bv.z, bv.w);
        #pragma unroll
        for (int r = 0; r < 5; ++r) {
            float a = sA[h][5 * ty + r];
            unsigned long long a2 = pack2(a, a);
            F2U v0, v1;
            ADD2(v0.u, a2, bp0);
            ADD2(v1.u, a2, bp1);
            v0.f.x = fmaxf(v0.f.x, 0.f); v0.f.y = fmaxf(v0.f.y, 0.f);
            v1.f.x = fmaxf(v1.f.x, 0.f); v1.f.y = fmaxf(v1.f.y, 0.f);
            FMA2(acc[r][0].u, v0.u, w2, acc[r][0].u);
            FMA2(acc[r][1].u, v1.u, w2, acc[r][1].u);
        }
    }

    float* dst = g_part + ((size_t)(s * BB + b) * NN) * NN;
    #pragma unroll
    for (int r = 0; r < 5; ++r) {
        float4 v = make_float4(acc[r][0].f.x, acc[r][0].f.y,
                               acc[r][1].f.x, acc[r][1].f.y);
        *(float4*)(dst + (size_t)(5 * ty + r) * NN + 4 * tx) = v;
    }
}

// ---------------------------------------------------------------------------
// Combine: sum 16 partials + b2, sigmoid, write out[b,i,j].
// ---------------------------------------------------------------------------
__global__ void combine_kernel(const float* __restrict__ b2,
                               float* __restrict__ out) {
    int b = blockIdx.y;
    int idx = blockIdx.x * 256 + threadIdx.x;
    if (idx >= NN * NN) return;

    float x = b2[0];
    #pragma unroll
    for (int s = 0; s < SPLIT; ++s)
        x += g_part[((size_t)(s * BB + b) * NN * NN) + idx];
    out[(size_t)b * NN * NN + idx] = 1.f / (1.f + expf(-x));
}

// ---------------------------------------------------------------------------
// Launch
// ---------------------------------------------------------------------------
extern "C" void kernel_launch(void* const* d_in, const int* in_sizes, int n_in,
                              void* d_out, int out_size) {
    const float* patch_tokens = (const float*)d_in[0];
    const float* boxes        = (const float*)d_in[1];
    const float* W1           = (const float*)d_in[2];
    const float* b1           = (const float*)d_in[3];
    const float* W2           = (const float*)d_in[4];
    const float* b2           = (const float*)d_in[5];
    float* out = (float*)d_out;

    prep_kernel<<<BB * TH + 384, DD>>>(patch_tokens, W1);
    pool_gather_kernel<<<M_ROWS, 256>>>(boxes);

    dim3 ggrid(24, 13);
    gemm_bf16_kernel<<<ggrid, 256>>>(b1);

    dim3 pgrid(SPLIT, BB);                       // 128 blocks, 500 thr
    pairwise_kernel<<<pgrid, 500>>>(W2);

    dim3 cgrid((NN * NN + 255) / 256, BB);       // (40, 8)
    combine_kernel<<<cgrid, 256>>>(b2, out);
}